// round 13
// baseline (speedup 1.0000x reference)
#include <cuda_runtime.h>
#include <cstdint>
#include <math.h>

// Problem dims (fixed by the reference)
#define TDIM 4096
#define CDIM 2048
#define NF   2048
#define N3   6144   // 3*NF

#define BM 128
#define BN 256      // block N tile (8 warps x 64x64 warp tiles)
#define BK 32
#define SW 32       // unpadded swizzled tile stride

// Scratch (fp32, pre-rounded to tf32 grid).
// g_xr / g_wt: K dim permuted in 16-groups (j -> 4*(j%4)+j/4, involution).
// g_qkv: Q and K feature columns permuted; V columns original.
// g_vt:  V^T [n][t] with t permuted in 16-groups.
// g_P:   post-softmax probabilities with column (t) dim permuted.
__device__ __align__(256) float g_qkv[(size_t)TDIM * N3];
__device__ __align__(256) float g_P[(size_t)TDIM * TDIM];
__device__ __align__(256) float g_vt[(size_t)NF * TDIM];
__device__ __align__(256) float g_xr[(size_t)TDIM * CDIM];
__device__ __align__(256) float g_wt[(size_t)N3 * CDIM];

__device__ __forceinline__ float f2tf32f(float x) {
    uint32_t u;
    asm("cvt.rna.tf32.f32 %0, %1;" : "=r"(u) : "f"(x));
    return __uint_as_float(u);
}

__device__ __forceinline__ void mma_tf32(float* d,
    uint32_t a0, uint32_t a1, uint32_t a2, uint32_t a3,
    uint32_t b0, uint32_t b1)
{
    asm volatile(
        "mma.sync.aligned.m16n8k8.row.col.f32.tf32.tf32.f32 "
        "{%0,%1,%2,%3}, {%4,%5,%6,%7}, {%8,%9}, {%0,%1,%2,%3};\n"
        : "+f"(d[0]), "+f"(d[1]), "+f"(d[2]), "+f"(d[3])
        : "r"(a0), "r"(a1), "r"(a2), "r"(a3), "r"(b0), "r"(b1));
}

__device__ __forceinline__ void cp16(float* smem_dst, const float* gsrc) {
    uint32_t s = (uint32_t)__cvta_generic_to_shared(smem_dst);
    asm volatile("cp.async.cg.shared.global [%0], [%1], 16;\n" :: "r"(s), "l"(gsrc));
}
#define CP_COMMIT() asm volatile("cp.async.commit_group;\n")
#define CP_WAIT0()  asm volatile("cp.async.wait_group 0;\n")

// permuted position of absolute index f (16-group involution)
__device__ __forceinline__ int perm16(int f) {
    int j = f & 15;
    return (f & ~15) + 4 * (j & 3) + (j >> 2);
}

// ---------------------------------------------------------------------------
// Swizzled tiles: ROWS x 32 floats, stride 32. float4 slot k4 of row r stored
// at slot (k4 ^ ((r&1)<<2)) -> LDS.128 conflict-free, cp.async conflict-free.
// ---------------------------------------------------------------------------
template <int ROWS>
__device__ __forceinline__ void load_sw(float* tile, const float* __restrict__ src,
                                        size_t ld, int tid)
{
    #pragma unroll
    for (int i = 0; i < ROWS * 8 / 256; i++) {
        int idx = tid + i * 256;
        int r = idx >> 3;
        int k4 = idx & 7;
        int sw = k4 ^ ((r & 1) << 2);
        cp16(tile + r * SW + sw * 4, src + (size_t)r * ld + k4 * 4);
    }
}

// Vectorized NT compute, 64x64 warp tile: A tile 128 rows, B tile 256 rows.
// acc[mt*8+nt][4], mt=0..3 (16-row steps), nt=0..7 (8-col steps).
__device__ __forceinline__ void compute_NT_big(const float* As, const float* Bs,
                                               float (*acc)[4], int wm, int wn,
                                               int g, int t4)
{
    const int x4 = (g & 1) << 2;
    #pragma unroll
    for (int q = 0; q < 2; q++) {
        const int koff = ((q * 4 + t4) ^ x4) * 4;
        float4 bv[8];
        #pragma unroll
        for (int nt = 0; nt < 8; nt++) {
            const int n = wn * 64 + nt * 8 + g;
            bv[nt] = *(const float4*)&Bs[n * SW + koff];
        }
        #pragma unroll
        for (int mt = 0; mt < 4; mt++) {
            const int m = wm * 64 + mt * 16 + g;
            float4 a0 = *(const float4*)&As[m * SW + koff];
            float4 a1 = *(const float4*)&As[(m + 8) * SW + koff];
            #pragma unroll
            for (int nt = 0; nt < 8; nt++)
                mma_tf32(acc[mt * 8 + nt],
                         __float_as_uint(a0.x), __float_as_uint(a1.x),
                         __float_as_uint(a0.y), __float_as_uint(a1.y),
                         __float_as_uint(bv[nt].x), __float_as_uint(bv[nt].y));
            #pragma unroll
            for (int nt = 0; nt < 8; nt++)
                mma_tf32(acc[mt * 8 + nt],
                         __float_as_uint(a0.z), __float_as_uint(a1.z),
                         __float_as_uint(a0.w), __float_as_uint(a1.w),
                         __float_as_uint(bv[nt].z), __float_as_uint(bv[nt].w));
        }
    }
}

#define SMEM_BIG (2 * (BM * SW + BN * SW) * (int)sizeof(float))   // 98304

// ---------------------------------------------------------------------------
// Prep kernels
// ---------------------------------------------------------------------------
__global__ __launch_bounds__(256)
void k_round_perm(const float* __restrict__ src, float* __restrict__ dst,
                  int rows, int cols)
{
    int total4 = rows * (cols >> 2);
    int i = blockIdx.x * 256 + threadIdx.x;
    int stride = gridDim.x * 256;
    for (; i < total4; i += stride) {
        int row = i / (cols >> 2);
        int c4 = i % (cols >> 2);
        int base = (c4 >> 2) << 4;
        int a = c4 & 3;
        const float* s = src + (size_t)row * cols + base;
        float4 v;
        v.x = f2tf32f(s[0 + a]);
        v.y = f2tf32f(s[4 + a]);
        v.z = f2tf32f(s[8 + a]);
        v.w = f2tf32f(s[12 + a]);
        *(float4*)(dst + (size_t)row * cols + base + 4 * a) = v;
    }
}

__global__ __launch_bounds__(256)
void k_transpose_round_perm(const float* __restrict__ src, float* __restrict__ dst)
{
    __shared__ float t[32][33];
    const int bx = blockIdx.x * 32;
    const int by = blockIdx.y * 32;
    const int tx = threadIdx.x & 31;
    const int ty = threadIdx.x >> 5;
    #pragma unroll
    for (int i = 0; i < 32; i += 8)
        t[ty + i][tx] = src[(size_t)(by + ty + i) * N3 + bx + tx];
    __syncthreads();
    const int kpos = by + (tx & 16) + 4 * (tx & 3) + ((tx & 15) >> 2);
    #pragma unroll
    for (int i = 0; i < 32; i += 8)
        dst[(size_t)(bx + ty + i) * CDIM + kpos] = f2tf32f(t[tx][ty + i]);
}

// V slice of g_qkv (t x n, rounded) -> g_vt[n][perm16(t)]
__global__ __launch_bounds__(256)
void k_transpose_v()
{
    __shared__ float t[32][33];
    const int bx = blockIdx.x * 32;   // over n (NF)
    const int by = blockIdx.y * 32;   // over t (TDIM)
    const int tx = threadIdx.x & 31;
    const int ty = threadIdx.x >> 5;
    #pragma unroll
    for (int i = 0; i < 32; i += 8)
        t[ty + i][tx] = g_qkv[(size_t)(by + ty + i) * N3 + 2 * NF + bx + tx];
    __syncthreads();
    const int kpos = by + (tx & 16) + 4 * (tx & 3) + ((tx & 15) >> 2);
    #pragma unroll
    for (int i = 0; i < 32; i += 8)
        g_vt[(size_t)(bx + ty + i) * TDIM + kpos] = t[tx][ty + i];
}

// ---------------------------------------------------------------------------
// Kernel 1: qkv = x @ W + b  (NT, 128x256 block). Q/K cols PERMUTED; V original.
// ---------------------------------------------------------------------------
__global__ __launch_bounds__(256, 1)
void k_gemm_qkv(const float* __restrict__ bias)
{
    extern __shared__ float sm[];
    float* As[2] = { sm,                          sm + BM * SW };
    float* Bs[2] = { sm + 2 * BM * SW,            sm + 2 * BM * SW + BN * SW };

    const int tid = threadIdx.x;
    const int lane = tid & 31, wid = tid >> 5;
    const int wm = wid & 1, wn = wid >> 1;
    const int g = lane >> 2, t4 = lane & 3;
    const int m0 = blockIdx.y * BM;
    const int n0 = blockIdx.x * BN;

    float acc[32][4];
    #pragma unroll
    for (int i = 0; i < 32; i++)
        #pragma unroll
        for (int j = 0; j < 4; j++) acc[i][j] = 0.f;

    const int nk = CDIM / BK;
    load_sw<BM>(As[0], g_xr + (size_t)m0 * CDIM, CDIM, tid);
    load_sw<BN>(Bs[0], g_wt + (size_t)n0 * CDIM, CDIM, tid);
    CP_COMMIT();

    int buf = 0;
    for (int it = 0; it < nk; it++) {
        CP_WAIT0();
        __syncthreads();
        if (it + 1 < nk) {
            const int kn = (it + 1) * BK;
            load_sw<BM>(As[buf ^ 1], g_xr + (size_t)m0 * CDIM + kn, CDIM, tid);
            load_sw<BN>(Bs[buf ^ 1], g_wt + (size_t)n0 * CDIM + kn, CDIM, tid);
            CP_COMMIT();
        }
        compute_NT_big(As[buf], Bs[buf], acc, wm, wn, g, t4);
        buf ^= 1;
    }

    const bool isV = (n0 >= 2 * NF);
    #pragma unroll
    for (int mt = 0; mt < 4; mt++) {
        const int row = m0 + wm * 64 + mt * 16 + g;
        #pragma unroll
        for (int nt = 0; nt < 8; nt++) {
            #pragma unroll
            for (int e = 0; e < 2; e++) {
                const int f = n0 + wn * 64 + nt * 8 + t4 * 2 + e;
                const float bv = bias[f];
                const int col = isV ? f : perm16(f);
                g_qkv[(size_t)row * N3 + col]       = f2tf32f(acc[mt*8+nt][e]     + bv);
                g_qkv[(size_t)(row + 8) * N3 + col] = f2tf32f(acc[mt*8+nt][2 + e] + bv);
            }
        }
    }
}

// ---------------------------------------------------------------------------
// Kernel 2: S = scale * Q @ K^T (NT, 128x256 block, masked-block skipping).
// ---------------------------------------------------------------------------
__global__ __launch_bounds__(256, 1)
void k_gemm_s(const int* __restrict__ n_padd_p)
{
    const int np = *n_padd_p;
    const int rm = blockIdx.y * BM;
    const int cn = blockIdx.x * BN;
    if (cn >= rm + BM) return;          // fully above diagonal
    if (cn + BN <= np) return;          // cols fully in padding
    if (rm + BM <= np) return;          // rows fully in padding

    extern __shared__ float sm[];
    float* As[2] = { sm,               sm + BM * SW };
    float* Ks[2] = { sm + 2 * BM * SW, sm + 2 * BM * SW + BN * SW };

    const int tid = threadIdx.x;
    const int lane = tid & 31, wid = tid >> 5;
    const int wm = wid & 1, wn = wid >> 1;
    const int g = lane >> 2, t4 = lane & 3;

    float acc[32][4];
    #pragma unroll
    for (int i = 0; i < 32; i++)
        #pragma unroll
        for (int j = 0; j < 4; j++) acc[i][j] = 0.f;

    const int nk = NF / BK;
    load_sw<BM>(As[0], g_qkv + (size_t)rm * N3, N3, tid);
    load_sw<BN>(Ks[0], g_qkv + (size_t)cn * N3 + NF, N3, tid);
    CP_COMMIT();

    int buf = 0;
    for (int it = 0; it < nk; it++) {
        CP_WAIT0();
        __syncthreads();
        if (it + 1 < nk) {
            const int kn = (it + 1) * BK;
            load_sw<BM>(As[buf ^ 1], g_qkv + (size_t)rm * N3 + kn, N3, tid);
            load_sw<BN>(Ks[buf ^ 1], g_qkv + (size_t)cn * N3 + NF + kn, N3, tid);
            CP_COMMIT();
        }
        compute_NT_big(As[buf], Ks[buf], acc, wm, wn, g, t4);
        buf ^= 1;
    }

    const float scale = rsqrtf((float)NF);
    #pragma unroll
    for (int mt = 0; mt < 4; mt++) {
        #pragma unroll
        for (int nt = 0; nt < 8; nt++) {
            const int row = rm + wm * 64 + mt * 16 + g;
            const int col = cn + wn * 64 + nt * 8 + t4 * 2;
            *(float2*)(g_P + (size_t)row * TDIM + col) =
                make_float2(acc[mt*8+nt][0] * scale, acc[mt*8+nt][1] * scale);
            *(float2*)(g_P + (size_t)(row + 8) * TDIM + col) =
                make_float2(acc[mt*8+nt][2] * scale, acc[mt*8+nt][3] * scale);
        }
    }
}

// ---------------------------------------------------------------------------
// Kernel 3: row softmax in-place on g_P; final pass permutes 16-col groups.
// ---------------------------------------------------------------------------
__global__ __launch_bounds__(256)
void k_softmax(const int* __restrict__ n_padd_p)
{
    const int r = blockIdx.x;
    const int np = *n_padd_p;
    const int tid = threadIdx.x;
    __shared__ float red[256];

    float* prow = g_P + (size_t)r * TDIM;

    if (r < np) {
        float4 z = make_float4(0.f, 0.f, 0.f, 0.f);
        for (int i = tid; i < TDIM / 4; i += 256)
            ((float4*)prow)[i] = z;
        return;
    }

    float m = -3.402823466e+38f;
    for (int c = np + tid; c <= r; c += 256) m = fmaxf(m, prow[c]);
    red[tid] = m; __syncthreads();
    for (int s = 128; s > 0; s >>= 1) {
        if (tid < s) red[tid] = fmaxf(red[tid], red[tid + s]);
        __syncthreads();
    }
    m = red[0];
    __syncthreads();

    for (int c = tid; c < np; c += 256) prow[c] = 0.f;
    for (int c = r + 1 + tid; c < TDIM; c += 256) prow[c] = 0.f;
    float sum = 0.f;
    for (int c = np + tid; c <= r; c += 256) {
        float e = __expf(prow[c] - m);
        prow[c] = e;
        sum += e;
    }
    red[tid] = sum; __syncthreads();
    for (int s = 128; s > 0; s >>= 1) {
        if (tid < s) red[tid] += red[tid + s];
        __syncthreads();
    }
    const float inv = 1.0f / red[0];
    __syncthreads();

    {
        const int base = tid * 16;
        float v[16];
        #pragma unroll
        for (int j = 0; j < 16; j += 4)
            *(float4*)&v[j] = *(const float4*)&prow[base + j];
        #pragma unroll
        for (int j = 0; j < 16; j++) v[j] = f2tf32f(v[j] * inv);
        #pragma unroll
        for (int a = 0; a < 4; a++) {
            float4 o = make_float4(v[a], v[4 + a], v[8 + a], v[12 + a]);
            *(float4*)&prow[base + 4 * a] = o;
        }
    }
}

// ---------------------------------------------------------------------------
// Kernel 4: y = P @ V (NT via g_vt, 128x256 block), K-range clipped.
// ---------------------------------------------------------------------------
__global__ __launch_bounds__(256, 1)
void k_gemm_pv(const int* __restrict__ n_padd_p, float* __restrict__ C)
{
    const int np = *n_padd_p;
    const int rm = blockIdx.y * BM;
    const int cn = blockIdx.x * BN;
    const int tid = threadIdx.x;
    const int lane = tid & 31, wid = tid >> 5;
    const int wm = wid & 1, wn = wid >> 1;
    const int g = lane >> 2, t4 = lane & 3;

    if (rm + BM <= np) {
        for (int idx = tid; idx < BM * (BN / 4); idx += 256) {
            int row = idx / (BN / 4);
            int c4 = idx % (BN / 4);
            ((float4*)(C + (size_t)(rm + row) * NF + cn))[c4] =
                make_float4(0.f, 0.f, 0.f, 0.f);
        }
        return;
    }

    const int kstart = np & ~(BK - 1);
    const int nk = (rm + BM - kstart) / BK;

    extern __shared__ float sm[];
    float* As[2] = { sm,               sm + BM * SW };
    float* Bs[2] = { sm + 2 * BM * SW, sm + 2 * BM * SW + BN * SW };

    float acc[32][4];
    #pragma unroll
    for (int i = 0; i < 32; i++)
        #pragma unroll
        for (int j = 0; j < 4; j++) acc[i][j] = 0.f;

    load_sw<BM>(As[0], g_P + (size_t)rm * TDIM + kstart, TDIM, tid);
    load_sw<BN>(Bs[0], g_vt + (size_t)cn * TDIM + kstart, TDIM, tid);
    CP_COMMIT();

    int buf = 0;
    for (int it = 0; it < nk; it++) {
        CP_WAIT0();
        __syncthreads();
        if (it + 1 < nk) {
            const int kn = kstart + (it + 1) * BK;
            load_sw<BM>(As[buf ^ 1], g_P + (size_t)rm * TDIM + kn, TDIM, tid);
            load_sw<BN>(Bs[buf ^ 1], g_vt + (size_t)cn * TDIM + kn, TDIM, tid);
            CP_COMMIT();
        }
        compute_NT_big(As[buf], Bs[buf], acc, wm, wn, g, t4);
        buf ^= 1;
    }

    #pragma unroll
    for (int mt = 0; mt < 4; mt++) {
        #pragma unroll
        for (int nt = 0; nt < 8; nt++) {
            const int row = rm + wm * 64 + mt * 16 + g;
            const int col = cn + wn * 64 + nt * 8 + t4 * 2;
            *(float2*)(C + (size_t)row * NF + col) =
                make_float2(acc[mt*8+nt][0], acc[mt*8+nt][1]);
            *(float2*)(C + (size_t)(row + 8) * NF + col) =
                make_float2(acc[mt*8+nt][2], acc[mt*8+nt][3]);
        }
    }
}

// ---------------------------------------------------------------------------
extern "C" void kernel_launch(void* const* d_in, const int* in_sizes, int n_in,
                              void* d_out, int out_size)
{
    const float* x  = (const float*)d_in[0];
    const float* W  = (const float*)d_in[1];
    const float* b  = (const float*)d_in[2];
    const int*   np = (const int*)d_in[3];
    float* y = (float*)d_out;
    (void)in_sizes; (void)n_in; (void)out_size;

    cudaFuncSetAttribute(k_gemm_qkv, cudaFuncAttributeMaxDynamicSharedMemorySize, SMEM_BIG);
    cudaFuncSetAttribute(k_gemm_s,   cudaFuncAttributeMaxDynamicSharedMemorySize, SMEM_BIG);
    cudaFuncSetAttribute(k_gemm_pv,  cudaFuncAttributeMaxDynamicSharedMemorySize, SMEM_BIG);

    float* xr; float* wt;
    cudaGetSymbolAddress((void**)&xr, g_xr);
    cudaGetSymbolAddress((void**)&wt, g_wt);

    dim3 t(256);
    k_round_perm<<<1024, t>>>(x, xr, TDIM, CDIM);
    k_transpose_round_perm<<<dim3(N3 / 32, CDIM / 32), t>>>(W, wt);
    k_gemm_qkv<<<dim3(N3 / BN, TDIM / BM), t, SMEM_BIG>>>(b);
    k_transpose_v<<<dim3(NF / 32, TDIM / 32), t>>>();
    k_gemm_s<<<dim3(TDIM / BN, TDIM / BM), t, SMEM_BIG>>>(np);
    k_softmax<<<TDIM, t>>>(np);
    k_gemm_pv<<<dim3(NF / BN, TDIM / BM), t, SMEM_BIG>>>(np, y);
}

// round 14
// speedup vs baseline: 1.1952x; 1.1952x over previous
#include <cuda_runtime.h>
#include <cstdint>
#include <math.h>

// Problem dims (fixed by the reference)
#define TDIM 4096
#define CDIM 2048
#define NF   2048
#define N3   6144   // 3*NF

#define BM 128
#define BN 128
#define BK 32
#define SW 32        // unpadded swizzled tile stride
#define NSTAGE 3

// Scratch (fp32, pre-rounded to tf32 grid).
// g_xr / g_wt: K dim permuted in 16-groups (j -> 4*(j%4)+j/4, involution).
// g_qkv: Q and K feature columns permuted; V columns original.
// g_vt:  V^T [n][t] with t permuted in 16-groups.
// g_P:   post-softmax probabilities with column (t) dim permuted.
__device__ __align__(256) float g_qkv[(size_t)TDIM * N3];
__device__ __align__(256) float g_P[(size_t)TDIM * TDIM];
__device__ __align__(256) float g_vt[(size_t)NF * TDIM];
__device__ __align__(256) float g_xr[(size_t)TDIM * CDIM];
__device__ __align__(256) float g_wt[(size_t)N3 * CDIM];

__device__ __forceinline__ float f2tf32f(float x) {
    uint32_t u;
    asm("cvt.rna.tf32.f32 %0, %1;" : "=r"(u) : "f"(x));
    return __uint_as_float(u);
}

__device__ __forceinline__ void mma_tf32(float* d,
    uint32_t a0, uint32_t a1, uint32_t a2, uint32_t a3,
    uint32_t b0, uint32_t b1)
{
    asm volatile(
        "mma.sync.aligned.m16n8k8.row.col.f32.tf32.tf32.f32 "
        "{%0,%1,%2,%3}, {%4,%5,%6,%7}, {%8,%9}, {%0,%1,%2,%3};\n"
        : "+f"(d[0]), "+f"(d[1]), "+f"(d[2]), "+f"(d[3])
        : "r"(a0), "r"(a1), "r"(a2), "r"(a3), "r"(b0), "r"(b1));
}

__device__ __forceinline__ void cp16(float* smem_dst, const float* gsrc) {
    uint32_t s = (uint32_t)__cvta_generic_to_shared(smem_dst);
    asm volatile("cp.async.cg.shared.global [%0], [%1], 16;\n" :: "r"(s), "l"(gsrc));
}
#define CP_COMMIT() asm volatile("cp.async.commit_group;\n")
#define CP_WAIT(n)  asm volatile("cp.async.wait_group %0;\n" :: "n"(n))

// permuted position of absolute index f (16-group involution)
__device__ __forceinline__ int perm16(int f) {
    int j = f & 15;
    return (f & ~15) + 4 * (j & 3) + (j >> 2);
}

// ---------------------------------------------------------------------------
// Swizzled tiles: 128 rows x 32 floats, stride 32. float4 slot k4 of row r
// stored at slot (k4 ^ ((r&1)<<2)) -> LDS.128 + cp.async conflict-free.
// ---------------------------------------------------------------------------
__device__ __forceinline__ void load_sw(float* tile, const float* __restrict__ src,
                                        size_t ld, int tid)
{
    #pragma unroll
    for (int i = 0; i < 4; i++) {
        int idx = tid + i * 256;
        int r = idx >> 3;
        int k4 = idx & 7;
        int sw = k4 ^ ((r & 1) << 2);
        cp16(tile + r * SW + sw * 4, src + (size_t)r * ld + k4 * 4);
    }
}

// Vectorized NT compute on swizzled tiles; K pre-permuted in 16-groups.
__device__ __forceinline__ void compute_NT_sw(const float* As, const float* Bs,
                                              float (*acc)[4], int wm, int wn, int g, int t4)
{
    const int x4 = (g & 1) << 2;
    #pragma unroll
    for (int q = 0; q < 2; q++) {
        const int koff = ((q * 4 + t4) ^ x4) * 4;
        float4 bv[4];
        #pragma unroll
        for (int nt = 0; nt < 4; nt++) {
            const int n = wn * 32 + nt * 8 + g;
            bv[nt] = *(const float4*)&Bs[n * SW + koff];
        }
        #pragma unroll
        for (int mt = 0; mt < 4; mt++) {
            const int m = wm * 64 + mt * 16 + g;
            float4 a0 = *(const float4*)&As[m * SW + koff];
            float4 a1 = *(const float4*)&As[(m + 8) * SW + koff];
            #pragma unroll
            for (int nt = 0; nt < 4; nt++)
                mma_tf32(acc[mt * 4 + nt],
                         __float_as_uint(a0.x), __float_as_uint(a1.x),
                         __float_as_uint(a0.y), __float_as_uint(a1.y),
                         __float_as_uint(bv[nt].x), __float_as_uint(bv[nt].y));
            #pragma unroll
            for (int nt = 0; nt < 4; nt++)
                mma_tf32(acc[mt * 4 + nt],
                         __float_as_uint(a0.z), __float_as_uint(a1.z),
                         __float_as_uint(a0.w), __float_as_uint(a1.w),
                         __float_as_uint(bv[nt].z), __float_as_uint(bv[nt].w));
        }
    }
}

#define STAGE_FLOATS (2 * BM * SW)                          // A+B per stage
#define SMEM_TOT (NSTAGE * STAGE_FLOATS * (int)sizeof(float))  // 98304

// ---------------------------------------------------------------------------
// Prep kernels
// ---------------------------------------------------------------------------
__global__ __launch_bounds__(256)
void k_round_perm(const float* __restrict__ src, float* __restrict__ dst,
                  int rows, int cols)
{
    int total4 = rows * (cols >> 2);
    int i = blockIdx.x * 256 + threadIdx.x;
    int stride = gridDim.x * 256;
    for (; i < total4; i += stride) {
        int row = i / (cols >> 2);
        int c4 = i % (cols >> 2);
        int base = (c4 >> 2) << 4;
        int a = c4 & 3;
        const float* s = src + (size_t)row * cols + base;
        float4 v;
        v.x = f2tf32f(s[0 + a]);
        v.y = f2tf32f(s[4 + a]);
        v.z = f2tf32f(s[8 + a]);
        v.w = f2tf32f(s[12 + a]);
        *(float4*)(dst + (size_t)row * cols + base + 4 * a) = v;
    }
}

__global__ __launch_bounds__(256)
void k_transpose_round_perm(const float* __restrict__ src, float* __restrict__ dst)
{
    __shared__ float t[32][33];
    const int bx = blockIdx.x * 32;
    const int by = blockIdx.y * 32;
    const int tx = threadIdx.x & 31;
    const int ty = threadIdx.x >> 5;
    #pragma unroll
    for (int i = 0; i < 32; i += 8)
        t[ty + i][tx] = src[(size_t)(by + ty + i) * N3 + bx + tx];
    __syncthreads();
    const int kpos = by + (tx & 16) + 4 * (tx & 3) + ((tx & 15) >> 2);
    #pragma unroll
    for (int i = 0; i < 32; i += 8)
        dst[(size_t)(bx + ty + i) * CDIM + kpos] = f2tf32f(t[tx][ty + i]);
}

// V slice of g_qkv (t x n, rounded) -> g_vt[n][perm16(t)]
__global__ __launch_bounds__(256)
void k_transpose_v()
{
    __shared__ float t[32][33];
    const int bx = blockIdx.x * 32;   // over n (NF)
    const int by = blockIdx.y * 32;   // over t (TDIM)
    const int tx = threadIdx.x & 31;
    const int ty = threadIdx.x >> 5;
    #pragma unroll
    for (int i = 0; i < 32; i += 8)
        t[ty + i][tx] = g_qkv[(size_t)(by + ty + i) * N3 + 2 * NF + bx + tx];
    __syncthreads();
    const int kpos = by + (tx & 16) + 4 * (tx & 3) + ((tx & 15) >> 2);
    #pragma unroll
    for (int i = 0; i < 32; i += 8)
        g_vt[(size_t)(bx + ty + i) * TDIM + kpos] = t[tx][ty + i];
}

// ---------------------------------------------------------------------------
// 3-stage pipelined mainloop macro body (A rows from pa, B rows from pb).
// ---------------------------------------------------------------------------
#define GEMM_MAINLOOP(pa, lda, pb, ldb, kstart, nk)                          \
    {                                                                        \
        if ((nk) > 0) { load_sw(sA(0), (pa) + (kstart), (lda), tid);         \
                        load_sw(sB(0), (pb) + (kstart), (ldb), tid);         \
                        CP_COMMIT(); }                                       \
        if ((nk) > 1) { load_sw(sA(1), (pa) + (kstart) + BK, (lda), tid);    \
                        load_sw(sB(1), (pb) + (kstart) + BK, (ldb), tid);    \
                        CP_COMMIT(); }                                       \
        for (int it = 0; it < (nk); it++) {                                  \
            if (it + 1 < (nk)) CP_WAIT(1); else CP_WAIT(0);                  \
            __syncthreads();                                                 \
            if (it + 2 < (nk)) {                                             \
                const int kn = (kstart) + (it + 2) * BK;                     \
                const int st = (it + 2) % NSTAGE;                            \
                load_sw(sA(st), (pa) + kn, (lda), tid);                      \
                load_sw(sB(st), (pb) + kn, (ldb), tid);                      \
                CP_COMMIT();                                                 \
            }                                                                \
            compute_NT_sw(sA(it % NSTAGE), sB(it % NSTAGE), acc, wm, wn, g, t4); \
        }                                                                    \
    }

#define sA(s) (sm + (s) * STAGE_FLOATS)
#define sB(s) (sm + (s) * STAGE_FLOATS + BM * SW)

// ---------------------------------------------------------------------------
// Kernel 1: qkv = x @ W + b  (NT). Q/K cols PERMUTED into g_qkv; V original.
// ---------------------------------------------------------------------------
__global__ __launch_bounds__(256, 2)
void k_gemm_qkv(const float* __restrict__ bias)
{
    extern __shared__ float sm[];
    const int tid = threadIdx.x;
    const int lane = tid & 31, wid = tid >> 5;
    const int wm = wid & 1, wn = wid >> 1;
    const int g = lane >> 2, t4 = lane & 3;
    const int m0 = blockIdx.y * BM;
    const int n0 = blockIdx.x * BN;

    float acc[16][4];
    #pragma unroll
    for (int i = 0; i < 16; i++)
        #pragma unroll
        for (int j = 0; j < 4; j++) acc[i][j] = 0.f;

    const float* pa = g_xr + (size_t)m0 * CDIM;
    const float* pb = g_wt + (size_t)n0 * CDIM;
    GEMM_MAINLOOP(pa, CDIM, pb, CDIM, 0, CDIM / BK);

    const bool isV = (n0 >= 2 * NF);
    #pragma unroll
    for (int mt = 0; mt < 4; mt++) {
        const int row = m0 + wm * 64 + mt * 16 + g;
        #pragma unroll
        for (int nt = 0; nt < 4; nt++) {
            #pragma unroll
            for (int e = 0; e < 2; e++) {
                const int f = n0 + wn * 32 + nt * 8 + t4 * 2 + e;
                const float bv = bias[f];
                const int col = isV ? f : perm16(f);
                g_qkv[(size_t)row * N3 + col]       = f2tf32f(acc[mt*4+nt][e]     + bv);
                g_qkv[(size_t)(row + 8) * N3 + col] = f2tf32f(acc[mt*4+nt][2 + e] + bv);
            }
        }
    }
}

// ---------------------------------------------------------------------------
// Kernel 2: S = scale * Q @ K^T (NT), masked-block skipping.
// ---------------------------------------------------------------------------
__global__ __launch_bounds__(256, 2)
void k_gemm_s(const int* __restrict__ n_padd_p)
{
    const int np = *n_padd_p;
    const int rm = blockIdx.y * BM;
    const int cn = blockIdx.x * BN;
    if (cn >= rm + BM) return;
    if (cn + BN <= np) return;
    if (rm + BM <= np) return;

    extern __shared__ float sm[];
    const int tid = threadIdx.x;
    const int lane = tid & 31, wid = tid >> 5;
    const int wm = wid & 1, wn = wid >> 1;
    const int g = lane >> 2, t4 = lane & 3;

    float acc[16][4];
    #pragma unroll
    for (int i = 0; i < 16; i++)
        #pragma unroll
        for (int j = 0; j < 4; j++) acc[i][j] = 0.f;

    const float* pa = g_qkv + (size_t)rm * N3;
    const float* pb = g_qkv + (size_t)cn * N3 + NF;
    GEMM_MAINLOOP(pa, N3, pb, N3, 0, NF / BK);

    const float scale = rsqrtf((float)NF);
    #pragma unroll
    for (int mt = 0; mt < 4; mt++) {
        #pragma unroll
        for (int nt = 0; nt < 4; nt++) {
            const int row = rm + wm * 64 + mt * 16 + g;
            const int col = cn + wn * 32 + nt * 8 + t4 * 2;
            *(float2*)(g_P + (size_t)row * TDIM + col) =
                make_float2(acc[mt*4+nt][0] * scale, acc[mt*4+nt][1] * scale);
            *(float2*)(g_P + (size_t)(row + 8) * TDIM + col) =
                make_float2(acc[mt*4+nt][2] * scale, acc[mt*4+nt][3] * scale);
        }
    }
}

// ---------------------------------------------------------------------------
// Kernel 3: row softmax in-place on g_P; final pass permutes 16-col groups.
// ---------------------------------------------------------------------------
__global__ __launch_bounds__(256)
void k_softmax(const int* __restrict__ n_padd_p)
{
    const int r = blockIdx.x;
    const int np = *n_padd_p;
    const int tid = threadIdx.x;
    __shared__ float red[256];

    float* prow = g_P + (size_t)r * TDIM;

    if (r < np) {
        float4 z = make_float4(0.f, 0.f, 0.f, 0.f);
        for (int i = tid; i < TDIM / 4; i += 256)
            ((float4*)prow)[i] = z;
        return;
    }

    float m = -3.402823466e+38f;
    for (int c = np + tid; c <= r; c += 256) m = fmaxf(m, prow[c]);
    red[tid] = m; __syncthreads();
    for (int s = 128; s > 0; s >>= 1) {
        if (tid < s) red[tid] = fmaxf(red[tid], red[tid + s]);
        __syncthreads();
    }
    m = red[0];
    __syncthreads();

    for (int c = tid; c < np; c += 256) prow[c] = 0.f;
    for (int c = r + 1 + tid; c < TDIM; c += 256) prow[c] = 0.f;
    float sum = 0.f;
    for (int c = np + tid; c <= r; c += 256) {
        float e = __expf(prow[c] - m);
        prow[c] = e;
        sum += e;
    }
    red[tid] = sum; __syncthreads();
    for (int s = 128; s > 0; s >>= 1) {
        if (tid < s) red[tid] += red[tid + s];
        __syncthreads();
    }
    const float inv = 1.0f / red[0];
    __syncthreads();

    {
        const int base = tid * 16;
        float v[16];
        #pragma unroll
        for (int j = 0; j < 16; j += 4)
            *(float4*)&v[j] = *(const float4*)&prow[base + j];
        #pragma unroll
        for (int j = 0; j < 16; j++) v[j] = f2tf32f(v[j] * inv);
        #pragma unroll
        for (int a = 0; a < 4; a++) {
            float4 o = make_float4(v[a], v[4 + a], v[8 + a], v[12 + a]);
            *(float4*)&prow[base + 4 * a] = o;
        }
    }
}

// ---------------------------------------------------------------------------
// Kernel 4: y = P @ V (NT via g_vt, both t-permuted), K-range clipped.
// ---------------------------------------------------------------------------
__global__ __launch_bounds__(256, 2)
void k_gemm_pv(const int* __restrict__ n_padd_p, float* __restrict__ C)
{
    const int np = *n_padd_p;
    const int rm = blockIdx.y * BM;
    const int cn = blockIdx.x * BN;
    const int tid = threadIdx.x;
    const int lane = tid & 31, wid = tid >> 5;
    const int wm = wid & 1, wn = wid >> 1;
    const int g = lane >> 2, t4 = lane & 3;

    if (rm + BM <= np) {
        for (int idx = tid; idx < BM * (BN / 4); idx += 256) {
            int row = idx / (BN / 4);
            int c4 = idx % (BN / 4);
            ((float4*)(C + (size_t)(rm + row) * NF + cn))[c4] =
                make_float4(0.f, 0.f, 0.f, 0.f);
        }
        return;
    }

    const int kstart = np & ~(BK - 1);
    const int nk = (rm + BM - kstart) / BK;

    extern __shared__ float sm[];

    float acc[16][4];
    #pragma unroll
    for (int i = 0; i < 16; i++)
        #pragma unroll
        for (int j = 0; j < 4; j++) acc[i][j] = 0.f;

    const float* pa = g_P + (size_t)rm * TDIM;
    const float* pb = g_vt + (size_t)cn * TDIM;
    GEMM_MAINLOOP(pa, TDIM, pb, TDIM, kstart, nk);

    #pragma unroll
    for (int mt = 0; mt < 4; mt++) {
        #pragma unroll
        for (int nt = 0; nt < 4; nt++) {
            const int row = rm + wm * 64 + mt * 16 + g;
            const int col = cn + wn * 32 + nt * 8 + t4 * 2;
            *(float2*)(C + (size_t)row * NF + col) =
                make_float2(acc[mt*4+nt][0], acc[mt*4+nt][1]);
            *(float2*)(C + (size_t)(row + 8) * NF + col) =
                make_float2(acc[mt*4+nt][2], acc[mt*4+nt][3]);
        }
    }
}

// ---------------------------------------------------------------------------
extern "C" void kernel_launch(void* const* d_in, const int* in_sizes, int n_in,
                              void* d_out, int out_size)
{
    const float* x  = (const float*)d_in[0];
    const float* W  = (const float*)d_in[1];
    const float* b  = (const float*)d_in[2];
    const int*   np = (const int*)d_in[3];
    float* y = (float*)d_out;
    (void)in_sizes; (void)n_in; (void)out_size;

    cudaFuncSetAttribute(k_gemm_qkv, cudaFuncAttributeMaxDynamicSharedMemorySize, SMEM_TOT);
    cudaFuncSetAttribute(k_gemm_s,   cudaFuncAttributeMaxDynamicSharedMemorySize, SMEM_TOT);
    cudaFuncSetAttribute(k_gemm_pv,  cudaFuncAttributeMaxDynamicSharedMemorySize, SMEM_TOT);

    float* xr; float* wt;
    cudaGetSymbolAddress((void**)&xr, g_xr);
    cudaGetSymbolAddress((void**)&wt, g_wt);

    dim3 t(256);
    k_round_perm<<<1024, t>>>(x, xr, TDIM, CDIM);
    k_transpose_round_perm<<<dim3(N3 / 32, CDIM / 32), t>>>(W, wt);
    k_gemm_qkv<<<dim3(N3 / BN, TDIM / BM), t, SMEM_TOT>>>(b);
    k_transpose_v<<<dim3(NF / 32, TDIM / 32), t>>>();
    k_gemm_s<<<dim3(TDIM / BN, TDIM / BM), t, SMEM_TOT>>>(np);
    k_softmax<<<TDIM, t>>>(np);
    k_gemm_pv<<<dim3(NF / BN, TDIM / BM), t, SMEM_TOT>>>(np, y);
}

// round 16
// speedup vs baseline: 1.2773x; 1.0687x over previous
#include <cuda_runtime.h>
#include <cstdint>
#include <math.h>

// Problem dims (fixed by the reference)
#define TDIM 4096
#define CDIM 2048
#define NF   2048
#define N3   6144   // 3*NF

#define BM 128
#define BN 128
#define BK 32
#define SW 32        // unpadded swizzled tile stride
#define NSTAGE 3
#define NTHR 128     // 4 warps; 64x64 warp tile; reg cap 255

// Scratch (fp32, pre-rounded to tf32 grid).
// g_xr / g_wt: K dim permuted in 16-groups (j -> 4*(j%4)+j/4, involution).
// g_qkv: Q and K feature columns permuted; V columns original.
// g_vt:  V^T [n][t] with t permuted in 16-groups.
// g_P:   post-softmax probabilities with column (t) dim permuted.
__device__ __align__(256) float g_qkv[(size_t)TDIM * N3];
__device__ __align__(256) float g_P[(size_t)TDIM * TDIM];
__device__ __align__(256) float g_vt[(size_t)NF * TDIM];
__device__ __align__(256) float g_xr[(size_t)TDIM * CDIM];
__device__ __align__(256) float g_wt[(size_t)N3 * CDIM];

__device__ __forceinline__ float f2tf32f(float x) {
    uint32_t u;
    asm("cvt.rna.tf32.f32 %0, %1;" : "=r"(u) : "f"(x));
    return __uint_as_float(u);
}

__device__ __forceinline__ void mma_tf32(float* d,
    uint32_t a0, uint32_t a1, uint32_t a2, uint32_t a3,
    uint32_t b0, uint32_t b1)
{
    asm volatile(
        "mma.sync.aligned.m16n8k8.row.col.f32.tf32.tf32.f32 "
        "{%0,%1,%2,%3}, {%4,%5,%6,%7}, {%8,%9}, {%0,%1,%2,%3};\n"
        : "+f"(d[0]), "+f"(d[1]), "+f"(d[2]), "+f"(d[3])
        : "r"(a0), "r"(a1), "r"(a2), "r"(a3), "r"(b0), "r"(b1));
}

__device__ __forceinline__ void cp16(float* smem_dst, const float* gsrc) {
    uint32_t s = (uint32_t)__cvta_generic_to_shared(smem_dst);
    asm volatile("cp.async.cg.shared.global [%0], [%1], 16;\n" :: "r"(s), "l"(gsrc));
}
#define CP_COMMIT() asm volatile("cp.async.commit_group;\n")
#define CP_WAIT(n)  asm volatile("cp.async.wait_group %0;\n" :: "n"(n))

// permuted position of absolute index f (16-group involution)
__device__ __forceinline__ int perm16(int f) {
    int j = f & 15;
    return (f & ~15) + 4 * (j & 3) + (j >> 2);
}

// ---------------------------------------------------------------------------
// Swizzled tiles: 128 rows x 32 floats, stride 32. float4 slot k4 of row r
// stored at slot (k4 ^ ((r&1)<<2)) -> LDS.128 + cp.async conflict-free.
// Loader for 128 threads: 8 float4s per thread per tile.
// ---------------------------------------------------------------------------
__device__ __forceinline__ void load_sw(float* tile, const float* __restrict__ src,
                                        size_t ld, int tid)
{
    #pragma unroll
    for (int i = 0; i < 8; i++) {
        int idx = tid + i * NTHR;
        int r = idx >> 3;
        int k4 = idx & 7;
        int sw = k4 ^ ((r & 1) << 2);
        cp16(tile + r * SW + sw * 4, src + (size_t)r * ld + k4 * 4);
    }
}

// Vectorized NT compute, 64x64 warp tile (4 warps cover 128x128).
// acc[mt*8+nt][4], mt=0..3 (16-row steps), nt=0..7 (8-col steps).
__device__ __forceinline__ void compute_NT64(const float* As, const float* Bs,
                                             float (*acc)[4], int wm, int wn,
                                             int g, int t4)
{
    const int x4 = (g & 1) << 2;
    #pragma unroll
    for (int q = 0; q < 2; q++) {
        const int koff = ((q * 4 + t4) ^ x4) * 4;
        float4 bv[8];
        #pragma unroll
        for (int nt = 0; nt < 8; nt++) {
            const int n = wn * 64 + nt * 8 + g;
            bv[nt] = *(const float4*)&Bs[n * SW + koff];
        }
        #pragma unroll
        for (int mt = 0; mt < 4; mt++) {
            const int m = wm * 64 + mt * 16 + g;
            float4 a0 = *(const float4*)&As[m * SW + koff];
            float4 a1 = *(const float4*)&As[(m + 8) * SW + koff];
            #pragma unroll
            for (int nt = 0; nt < 8; nt++)
                mma_tf32(acc[mt * 8 + nt],
                         __float_as_uint(a0.x), __float_as_uint(a1.x),
                         __float_as_uint(a0.y), __float_as_uint(a1.y),
                         __float_as_uint(bv[nt].x), __float_as_uint(bv[nt].y));
            #pragma unroll
            for (int nt = 0; nt < 8; nt++)
                mma_tf32(acc[mt * 8 + nt],
                         __float_as_uint(a0.z), __float_as_uint(a1.z),
                         __float_as_uint(a0.w), __float_as_uint(a1.w),
                         __float_as_uint(bv[nt].z), __float_as_uint(bv[nt].w));
        }
    }
}

#define STAGE_FLOATS (2 * BM * SW)                              // A+B per stage
#define SMEM_TOT (NSTAGE * STAGE_FLOATS * (int)sizeof(float))   // 98304

// ---------------------------------------------------------------------------
// Prep kernels (256 threads)
// ---------------------------------------------------------------------------
__global__ __launch_bounds__(256)
void k_round_perm(const float* __restrict__ src, float* __restrict__ dst,
                  int rows, int cols)
{
    int total4 = rows * (cols >> 2);
    int i = blockIdx.x * 256 + threadIdx.x;
    int stride = gridDim.x * 256;
    for (; i < total4; i += stride) {
        int row = i / (cols >> 2);
        int c4 = i % (cols >> 2);
        int base = (c4 >> 2) << 4;
        int a = c4 & 3;
        const float* s = src + (size_t)row * cols + base;
        float4 v;
        v.x = f2tf32f(s[0 + a]);
        v.y = f2tf32f(s[4 + a]);
        v.z = f2tf32f(s[8 + a]);
        v.w = f2tf32f(s[12 + a]);
        *(float4*)(dst + (size_t)row * cols + base + 4 * a) = v;
    }
}

__global__ __launch_bounds__(256)
void k_transpose_round_perm(const float* __restrict__ src, float* __restrict__ dst)
{
    __shared__ float t[32][33];
    const int bx = blockIdx.x * 32;
    const int by = blockIdx.y * 32;
    const int tx = threadIdx.x & 31;
    const int ty = threadIdx.x >> 5;
    #pragma unroll
    for (int i = 0; i < 32; i += 8)
        t[ty + i][tx] = src[(size_t)(by + ty + i) * N3 + bx + tx];
    __syncthreads();
    const int kpos = by + (tx & 16) + 4 * (tx & 3) + ((tx & 15) >> 2);
    #pragma unroll
    for (int i = 0; i < 32; i += 8)
        dst[(size_t)(bx + ty + i) * CDIM + kpos] = f2tf32f(t[tx][ty + i]);
}

// V slice of g_qkv (t x n, rounded) -> g_vt[n][perm16(t)]
__global__ __launch_bounds__(256)
void k_transpose_v()
{
    __shared__ float t[32][33];
    const int bx = blockIdx.x * 32;   // over n (NF)
    const int by = blockIdx.y * 32;   // over t (TDIM)
    const int tx = threadIdx.x & 31;
    const int ty = threadIdx.x >> 5;
    #pragma unroll
    for (int i = 0; i < 32; i += 8)
        t[ty + i][tx] = g_qkv[(size_t)(by + ty + i) * N3 + 2 * NF + bx + tx];
    __syncthreads();
    const int kpos = by + (tx & 16) + 4 * (tx & 3) + ((tx & 15) >> 2);
    #pragma unroll
    for (int i = 0; i < 32; i += 8)
        g_vt[(size_t)(bx + ty + i) * TDIM + kpos] = t[tx][ty + i];
}

// ---------------------------------------------------------------------------
// 3-stage pipelined mainloop (A rows from pa, B rows from pb).
// ---------------------------------------------------------------------------
#define GEMM_MAINLOOP(pa, lda, pb, ldb, kstart, nk)                          \
    {                                                                        \
        if ((nk) > 0) { load_sw(sA(0), (pa) + (kstart), (lda), tid);         \
                        load_sw(sB(0), (pb) + (kstart), (ldb), tid);         \
                        CP_COMMIT(); }                                       \
        if ((nk) > 1) { load_sw(sA(1), (pa) + (kstart) + BK, (lda), tid);    \
                        load_sw(sB(1), (pb) + (kstart) + BK, (ldb), tid);    \
                        CP_COMMIT(); }                                       \
        for (int it = 0; it < (nk); it++) {                                  \
            if (it + 1 < (nk)) CP_WAIT(1); else CP_WAIT(0);                  \
            __syncthreads();                                                 \
            if (it + 2 < (nk)) {                                             \
                const int kn = (kstart) + (it + 2) * BK;                     \
                const int st = (it + 2) % NSTAGE;                            \
                load_sw(sA(st), (pa) + kn, (lda), tid);                      \
                load_sw(sB(st), (pb) + kn, (ldb), tid);                      \
                CP_COMMIT();                                                 \
            }                                                                \
            compute_NT64(sA(it % NSTAGE), sB(it % NSTAGE), acc, wm, wn, g, t4); \
        }                                                                    \
    }

#define sA(s) (sm + (s) * STAGE_FLOATS)
#define sB(s) (sm + (s) * STAGE_FLOATS + BM * SW)

// ---------------------------------------------------------------------------
// Kernel 1: qkv = x @ W + b  (NT). Q/K cols PERMUTED into g_qkv; V original.
// ---------------------------------------------------------------------------
__global__ __launch_bounds__(NTHR, 2)
void k_gemm_qkv(const float* __restrict__ bias)
{
    extern __shared__ float sm[];
    const int tid = threadIdx.x;
    const int lane = tid & 31, wid = tid >> 5;
    const int wm = wid & 1, wn = wid >> 1;     // 2x2 warps over 128x128
    const int g = lane >> 2, t4 = lane & 3;
    const int m0 = blockIdx.y * BM;
    const int n0 = blockIdx.x * BN;

    float acc[32][4];
    #pragma unroll
    for (int i = 0; i < 32; i++)
        #pragma unroll
        for (int j = 0; j < 4; j++) acc[i][j] = 0.f;

    const float* pa = g_xr + (size_t)m0 * CDIM;
    const float* pb = g_wt + (size_t)n0 * CDIM;
    GEMM_MAINLOOP(pa, CDIM, pb, CDIM, 0, CDIM / BK);

    const bool isV = (n0 >= 2 * NF);
    #pragma unroll
    for (int mt = 0; mt < 4; mt++) {
        const int row = m0 + wm * 64 + mt * 16 + g;
        #pragma unroll
        for (int nt = 0; nt < 8; nt++) {
            #pragma unroll
            for (int e = 0; e < 2; e++) {
                const int f = n0 + wn * 64 + nt * 8 + t4 * 2 + e;
                const float bv = bias[f];
                const int col = isV ? f : perm16(f);
                g_qkv[(size_t)row * N3 + col]       = f2tf32f(acc[mt*8+nt][e]     + bv);
                g_qkv[(size_t)(row + 8) * N3 + col] = f2tf32f(acc[mt*8+nt][2 + e] + bv);
            }
        }
    }
}

// ---------------------------------------------------------------------------
// Kernel 2: S = scale * Q @ K^T (NT), masked-block skipping.
// ---------------------------------------------------------------------------
__global__ __launch_bounds__(NTHR, 2)
void k_gemm_s(const int* __restrict__ n_padd_p)
{
    const int np = *n_padd_p;
    const int rm = blockIdx.y * BM;
    const int cn = blockIdx.x * BN;
    if (cn >= rm + BM) return;
    if (cn + BN <= np) return;
    if (rm + BM <= np) return;

    extern __shared__ float sm[];
    const int tid = threadIdx.x;
    const int lane = tid & 31, wid = tid >> 5;
    const int wm = wid & 1, wn = wid >> 1;
    const int g = lane >> 2, t4 = lane & 3;

    float acc[32][4];
    #pragma unroll
    for (int i = 0; i < 32; i++)
        #pragma unroll
        for (int j = 0; j < 4; j++) acc[i][j] = 0.f;

    const float* pa = g_qkv + (size_t)rm * N3;
    const float* pb = g_qkv + (size_t)cn * N3 + NF;
    GEMM_MAINLOOP(pa, N3, pb, N3, 0, NF / BK);

    const float scale = rsqrtf((float)NF);
    #pragma unroll
    for (int mt = 0; mt < 4; mt++) {
        #pragma unroll
        for (int nt = 0; nt < 8; nt++) {
            const int row = rm + wm * 64 + mt * 16 + g;
            const int col = cn + wn * 64 + nt * 8 + t4 * 2;
            *(float2*)(g_P + (size_t)row * TDIM + col) =
                make_float2(acc[mt*8+nt][0] * scale, acc[mt*8+nt][1] * scale);
            *(float2*)(g_P + (size_t)(row + 8) * TDIM + col) =
                make_float2(acc[mt*8+nt][2] * scale, acc[mt*8+nt][3] * scale);
        }
    }
}

// ---------------------------------------------------------------------------
// Kernel 3: row softmax in-place on g_P; final pass permutes 16-col groups.
// ---------------------------------------------------------------------------
__global__ __launch_bounds__(256)
void k_softmax(const int* __restrict__ n_padd_p)
{
    const int r = blockIdx.x;
    const int np = *n_padd_p;
    const int tid = threadIdx.x;
    __shared__ float red[256];

    float* prow = g_P + (size_t)r * TDIM;

    if (r < np) {
        float4 z = make_float4(0.f, 0.f, 0.f, 0.f);
        for (int i = tid; i < TDIM / 4; i += 256)
            ((float4*)prow)[i] = z;
        return;
    }

    float m = -3.402823466e+38f;
    for (int c = np + tid; c <= r; c += 256) m = fmaxf(m, prow[c]);
    red[tid] = m; __syncthreads();
    for (int s = 128; s > 0; s >>= 1) {
        if (tid < s) red[tid] = fmaxf(red[tid], red[tid + s]);
        __syncthreads();
    }
    m = red[0];
    __syncthreads();

    for (int c = tid; c < np; c += 256) prow[c] = 0.f;
    for (int c = r + 1 + tid; c < TDIM; c += 256) prow[c] = 0.f;
    float sum = 0.f;
    for (int c = np + tid; c <= r; c += 256) {
        float e = __expf(prow[c] - m);
        prow[c] = e;
        sum += e;
    }
    red[tid] = sum; __syncthreads();
    for (int s = 128; s > 0; s >>= 1) {
        if (tid < s) red[tid] += red[tid + s];
        __syncthreads();
    }
    const float inv = 1.0f / red[0];
    __syncthreads();

    {
        const int base = tid * 16;
        float v[16];
        #pragma unroll
        for (int j = 0; j < 16; j += 4)
            *(float4*)&v[j] = *(const float4*)&prow[base + j];
        #pragma unroll
        for (int j = 0; j < 16; j++) v[j] = f2tf32f(v[j] * inv);
        #pragma unroll
        for (int a = 0; a < 4; a++) {
            float4 o = make_float4(v[a], v[4 + a], v[8 + a], v[12 + a]);
            *(float4*)&prow[base + 4 * a] = o;
        }
    }
}

// ---------------------------------------------------------------------------
// Kernel 4: y = P @ V (NT via g_vt, both t-permuted), K-range clipped.
// ---------------------------------------------------------------------------
__global__ __launch_bounds__(NTHR, 2)
void k_gemm_pv(const int* __restrict__ n_padd_p, float* __restrict__ C)
{
    const int np = *n_padd_p;
    const int rm = blockIdx.y * BM;
    const int cn = blockIdx.x * BN;
    const int tid = threadIdx.x;
    const int lane = tid & 31, wid = tid >> 5;
    const int wm = wid & 1, wn = wid >> 1;
    const int g = lane >> 2, t4 = lane & 3;

    if (rm + BM <= np) {
        for (int idx = tid; idx < BM * (BN / 4); idx += NTHR) {
            int row = idx / (BN / 4);
            int c4 = idx % (BN / 4);
            ((float4*)(C + (size_t)(rm + row) * NF + cn))[c4] =
                make_float4(0.f, 0.f, 0.f, 0.f);
        }
        return;
    }

    const int kstart = np & ~(BK - 1);
    const int nk = (rm + BM - kstart) / BK;

    extern __shared__ float sm[];

    float acc[32][4];
    #pragma unroll
    for (int i = 0; i < 32; i++)
        #pragma unroll
        for (int j = 0; j < 4; j++) acc[i][j] = 0.f;

    const float* pa = g_P + (size_t)rm * TDIM;
    const float* pb = g_vt + (size_t)cn * TDIM;
    GEMM_MAINLOOP(pa, TDIM, pb, TDIM, kstart, nk);

    #pragma unroll
    for (int mt = 0; mt < 4; mt++) {
        #pragma unroll
        for (int nt = 0; nt < 8; nt++) {
            const int row = rm + wm * 64 + mt * 16 + g;
            const int col = cn + wn * 64 + nt * 8 + t4 * 2;
            *(float2*)(C + (size_t)row * NF + col) =
                make_float2(acc[mt*8+nt][0], acc[mt*8+nt][1]);
            *(float2*)(C + (size_t)(row + 8) * NF + col) =
                make_float2(acc[mt*8+nt][2], acc[mt*8+nt][3]);
        }
    }
}

// ---------------------------------------------------------------------------
extern "C" void kernel_launch(void* const* d_in, const int* in_sizes, int n_in,
                              void* d_out, int out_size)
{
    const float* x  = (const float*)d_in[0];
    const float* W  = (const float*)d_in[1];
    const float* b  = (const float*)d_in[2];
    const int*   np = (const int*)d_in[3];
    float* y = (float*)d_out;
    (void)in_sizes; (void)n_in; (void)out_size;

    cudaFuncSetAttribute(k_gemm_qkv, cudaFuncAttributeMaxDynamicSharedMemorySize, SMEM_TOT);
    cudaFuncSetAttribute(k_gemm_s,   cudaFuncAttributeMaxDynamicSharedMemorySize, SMEM_TOT);
    cudaFuncSetAttribute(k_gemm_pv,  cudaFuncAttributeMaxDynamicSharedMemorySize, SMEM_TOT);

    float* xr; float* wt;
    cudaGetSymbolAddress((void**)&xr, g_xr);
    cudaGetSymbolAddress((void**)&wt, g_wt);

    dim3 t256(256);
    dim3 tg(NTHR);
    k_round_perm<<<1024, t256>>>(x, xr, TDIM, CDIM);
    k_transpose_round_perm<<<dim3(N3 / 32, CDIM / 32), t256>>>(W, wt);
    k_gemm_qkv<<<dim3(N3 / BN, TDIM / BM), tg, SMEM_TOT>>>(b);
    k_transpose_v<<<dim3(NF / 32, TDIM / 32), t256>>>();
    k_gemm_s<<<dim3(TDIM / BN, TDIM / BM), tg, SMEM_TOT>>>(np);
    k_softmax<<<TDIM, t256>>>(np);
    k_gemm_pv<<<dim3(NF / BN, TDIM / BM), tg, SMEM_TOT>>>(np, y);
}

// round 17
// speedup vs baseline: 1.3378x; 1.0474x over previous
#include <cuda_runtime.h>
#include <cstdint>
#include <math.h>

// Problem dims (fixed by the reference)
#define TDIM 4096
#define CDIM 2048
#define NF   2048
#define N3   6144   // 3*NF

#define BM 128
#define BN 128
#define BK 32
#define SW 32        // unpadded swizzled tile stride
#define NSTAGE 3
#define NTHR 128     // 4 warps; 64x64 warp tile; reg cap 255

// Scratch (fp32, pre-rounded to tf32 grid).
// g_xr / g_wt: K dim permuted in 16-groups (j -> 4*(j%4)+j/4, involution).
// g_qkv: Q and K feature columns permuted; V columns original.
// g_vt:  V^T [n][t] with t permuted in 16-groups.
// g_P:   post-softmax probabilities with column (t) dim permuted.
__device__ __align__(256) float g_qkv[(size_t)TDIM * N3];
__device__ __align__(256) float g_P[(size_t)TDIM * TDIM];
__device__ __align__(256) float g_vt[(size_t)NF * TDIM];
__device__ __align__(256) float g_xr[(size_t)TDIM * CDIM];
__device__ __align__(256) float g_wt[(size_t)N3 * CDIM];

__device__ __forceinline__ float f2tf32f(float x) {
    uint32_t u;
    asm("cvt.rna.tf32.f32 %0, %1;" : "=r"(u) : "f"(x));
    return __uint_as_float(u);
}

__device__ __forceinline__ void mma_tf32(float* d,
    uint32_t a0, uint32_t a1, uint32_t a2, uint32_t a3,
    uint32_t b0, uint32_t b1)
{
    asm volatile(
        "mma.sync.aligned.m16n8k8.row.col.f32.tf32.tf32.f32 "
        "{%0,%1,%2,%3}, {%4,%5,%6,%7}, {%8,%9}, {%0,%1,%2,%3};\n"
        : "+f"(d[0]), "+f"(d[1]), "+f"(d[2]), "+f"(d[3])
        : "r"(a0), "r"(a1), "r"(a2), "r"(a3), "r"(b0), "r"(b1));
}

__device__ __forceinline__ void cp16(float* smem_dst, const float* gsrc) {
    uint32_t s = (uint32_t)__cvta_generic_to_shared(smem_dst);
    asm volatile("cp.async.cg.shared.global [%0], [%1], 16;\n" :: "r"(s), "l"(gsrc));
}
#define CP_COMMIT() asm volatile("cp.async.commit_group;\n")
#define CP_WAIT(n)  asm volatile("cp.async.wait_group %0;\n" :: "n"(n))

// permuted position of absolute index f (16-group involution)
__device__ __forceinline__ int perm16(int f) {
    int j = f & 15;
    return (f & ~15) + 4 * (j & 3) + (j >> 2);
}

// ---------------------------------------------------------------------------
// Swizzled tiles: 128 rows x 32 floats, stride 32. float4 slot k4 of row r
// stored at slot (k4 ^ ((r&1)<<2)) -> LDS.128 + cp.async conflict-free.
// Loader for 128 threads: 8 float4s per thread per tile.
// ---------------------------------------------------------------------------
__device__ __forceinline__ void load_sw(float* tile, const float* __restrict__ src,
                                        size_t ld, int tid)
{
    #pragma unroll
    for (int i = 0; i < 8; i++) {
        int idx = tid + i * NTHR;
        int r = idx >> 3;
        int k4 = idx & 7;
        int sw = k4 ^ ((r & 1) << 2);
        cp16(tile + r * SW + sw * 4, src + (size_t)r * ld + k4 * 4);
    }
}

// Vectorized NT compute, 64x64 warp tile (4 warps cover 128x128).
__device__ __forceinline__ void compute_NT64(const float* As, const float* Bs,
                                             float (*acc)[4], int wm, int wn,
                                             int g, int t4)
{
    const int x4 = (g & 1) << 2;
    #pragma unroll
    for (int q = 0; q < 2; q++) {
        const int koff = ((q * 4 + t4) ^ x4) * 4;
        float4 bv[8];
        #pragma unroll
        for (int nt = 0; nt < 8; nt++) {
            const int n = wn * 64 + nt * 8 + g;
            bv[nt] = *(const float4*)&Bs[n * SW + koff];
        }
        #pragma unroll
        for (int mt = 0; mt < 4; mt++) {
            const int m = wm * 64 + mt * 16 + g;
            float4 a0 = *(const float4*)&As[m * SW + koff];
            float4 a1 = *(const float4*)&As[(m + 8) * SW + koff];
            #pragma unroll
            for (int nt = 0; nt < 8; nt++)
                mma_tf32(acc[mt * 8 + nt],
                         __float_as_uint(a0.x), __float_as_uint(a1.x),
                         __float_as_uint(a0.y), __float_as_uint(a1.y),
                         __float_as_uint(bv[nt].x), __float_as_uint(bv[nt].y));
            #pragma unroll
            for (int nt = 0; nt < 8; nt++)
                mma_tf32(acc[mt * 8 + nt],
                         __float_as_uint(a0.z), __float_as_uint(a1.z),
                         __float_as_uint(a0.w), __float_as_uint(a1.w),
                         __float_as_uint(bv[nt].z), __float_as_uint(bv[nt].w));
        }
    }
}

#define STAGE_FLOATS (2 * BM * SW)                              // A+B per stage
#define SMEM_TOT (NSTAGE * STAGE_FLOATS * (int)sizeof(float))   // 98304

// ---------------------------------------------------------------------------
// Prep kernels (256 threads)
// ---------------------------------------------------------------------------
__global__ __launch_bounds__(256)
void k_round_perm(const float* __restrict__ src, float* __restrict__ dst,
                  int rows, int cols)
{
    int total4 = rows * (cols >> 2);
    int i = blockIdx.x * 256 + threadIdx.x;
    int stride = gridDim.x * 256;
    for (; i < total4; i += stride) {
        int row = i / (cols >> 2);
        int c4 = i % (cols >> 2);
        int base = (c4 >> 2) << 4;
        int a = c4 & 3;
        const float* s = src + (size_t)row * cols + base;
        float4 v;
        v.x = f2tf32f(s[0 + a]);
        v.y = f2tf32f(s[4 + a]);
        v.z = f2tf32f(s[8 + a]);
        v.w = f2tf32f(s[12 + a]);
        *(float4*)(dst + (size_t)row * cols + base + 4 * a) = v;
    }
}

__global__ __launch_bounds__(256)
void k_transpose_round_perm(const float* __restrict__ src, float* __restrict__ dst)
{
    __shared__ float t[32][33];
    const int bx = blockIdx.x * 32;
    const int by = blockIdx.y * 32;
    const int tx = threadIdx.x & 31;
    const int ty = threadIdx.x >> 5;
    #pragma unroll
    for (int i = 0; i < 32; i += 8)
        t[ty + i][tx] = src[(size_t)(by + ty + i) * N3 + bx + tx];
    __syncthreads();
    const int kpos = by + (tx & 16) + 4 * (tx & 3) + ((tx & 15) >> 2);
    #pragma unroll
    for (int i = 0; i < 32; i += 8)
        dst[(size_t)(bx + ty + i) * CDIM + kpos] = f2tf32f(t[tx][ty + i]);
}

// V slice of g_qkv (t x n, rounded) -> g_vt[n][perm16(t)]
__global__ __launch_bounds__(256)
void k_transpose_v()
{
    __shared__ float t[32][33];
    const int bx = blockIdx.x * 32;   // over n (NF)
    const int by = blockIdx.y * 32;   // over t (TDIM)
    const int tx = threadIdx.x & 31;
    const int ty = threadIdx.x >> 5;
    #pragma unroll
    for (int i = 0; i < 32; i += 8)
        t[ty + i][tx] = g_qkv[(size_t)(by + ty + i) * N3 + 2 * NF + bx + tx];
    __syncthreads();
    const int kpos = by + (tx & 16) + 4 * (tx & 3) + ((tx & 15) >> 2);
    #pragma unroll
    for (int i = 0; i < 32; i += 8)
        g_vt[(size_t)(bx + ty + i) * TDIM + kpos] = t[tx][ty + i];
}

// ---------------------------------------------------------------------------
// 3-stage pipelined mainloop (A rows from pa, B rows from pb).
// ---------------------------------------------------------------------------
#define GEMM_MAINLOOP(pa, lda, pb, ldb, kstart, nk)                          \
    {                                                                        \
        if ((nk) > 0) { load_sw(sA(0), (pa) + (kstart), (lda), tid);         \
                        load_sw(sB(0), (pb) + (kstart), (ldb), tid);         \
                        CP_COMMIT(); }                                       \
        if ((nk) > 1) { load_sw(sA(1), (pa) + (kstart) + BK, (lda), tid);    \
                        load_sw(sB(1), (pb) + (kstart) + BK, (ldb), tid);    \
                        CP_COMMIT(); }                                       \
        for (int it = 0; it < (nk); it++) {                                  \
            if (it + 1 < (nk)) CP_WAIT(1); else CP_WAIT(0);                  \
            __syncthreads();                                                 \
            if (it + 2 < (nk)) {                                             \
                const int kn = (kstart) + (it + 2) * BK;                     \
                const int st = (it + 2) % NSTAGE;                            \
                load_sw(sA(st), (pa) + kn, (lda), tid);                      \
                load_sw(sB(st), (pb) + kn, (ldb), tid);                      \
                CP_COMMIT();                                                 \
            }                                                                \
            compute_NT64(sA(it % NSTAGE), sB(it % NSTAGE), acc, wm, wn, g, t4); \
        }                                                                    \
    }

#define sA(s) (sm + (s) * STAGE_FLOATS)
#define sB(s) (sm + (s) * STAGE_FLOATS + BM * SW)

// ---------------------------------------------------------------------------
// Kernel 1: qkv = x @ W + b  (NT). Q/K cols PERMUTED into g_qkv; V original.
// Skips block rows entirely inside the left padding (their outputs are
// provably never consumed downstream).
// ---------------------------------------------------------------------------
__global__ __launch_bounds__(NTHR, 2)
void k_gemm_qkv(const float* __restrict__ bias, const int* __restrict__ n_padd_p)
{
    const int m0 = blockIdx.y * BM;
    const int np = *n_padd_p;
    if (m0 + BM <= np) return;   // Q/K/V rows < np are never used

    extern __shared__ float sm[];
    const int tid = threadIdx.x;
    const int lane = tid & 31, wid = tid >> 5;
    const int wm = wid & 1, wn = wid >> 1;     // 2x2 warps over 128x128
    const int g = lane >> 2, t4 = lane & 3;
    const int n0 = blockIdx.x * BN;

    float acc[32][4];
    #pragma unroll
    for (int i = 0; i < 32; i++)
        #pragma unroll
        for (int j = 0; j < 4; j++) acc[i][j] = 0.f;

    const float* pa = g_xr + (size_t)m0 * CDIM;
    const float* pb = g_wt + (size_t)n0 * CDIM;
    GEMM_MAINLOOP(pa, CDIM, pb, CDIM, 0, CDIM / BK);

    const bool isV = (n0 >= 2 * NF);
    #pragma unroll
    for (int mt = 0; mt < 4; mt++) {
        const int row = m0 + wm * 64 + mt * 16 + g;
        #pragma unroll
        for (int nt = 0; nt < 8; nt++) {
            #pragma unroll
            for (int e = 0; e < 2; e++) {
                const int f = n0 + wn * 64 + nt * 8 + t4 * 2 + e;
                const float bv = bias[f];
                const int col = isV ? f : perm16(f);
                g_qkv[(size_t)row * N3 + col]       = f2tf32f(acc[mt*8+nt][e]     + bv);
                g_qkv[(size_t)(row + 8) * N3 + col] = f2tf32f(acc[mt*8+nt][2 + e] + bv);
            }
        }
    }
}

// ---------------------------------------------------------------------------
// Kernel 2: S = scale * Q @ K^T (NT), masked-block skipping.
// ---------------------------------------------------------------------------
__global__ __launch_bounds__(NTHR, 2)
void k_gemm_s(const int* __restrict__ n_padd_p)
{
    const int np = *n_padd_p;
    const int rm = blockIdx.y * BM;
    const int cn = blockIdx.x * BN;
    if (cn >= rm + BM) return;
    if (cn + BN <= np) return;
    if (rm + BM <= np) return;

    extern __shared__ float sm[];
    const int tid = threadIdx.x;
    const int lane = tid & 31, wid = tid >> 5;
    const int wm = wid & 1, wn = wid >> 1;
    const int g = lane >> 2, t4 = lane & 3;

    float acc[32][4];
    #pragma unroll
    for (int i = 0; i < 32; i++)
        #pragma unroll
        for (int j = 0; j < 4; j++) acc[i][j] = 0.f;

    const float* pa = g_qkv + (size_t)rm * N3;
    const float* pb = g_qkv + (size_t)cn * N3 + NF;
    GEMM_MAINLOOP(pa, N3, pb, N3, 0, NF / BK);

    const float scale = rsqrtf((float)NF);
    #pragma unroll
    for (int mt = 0; mt < 4; mt++) {
        #pragma unroll
        for (int nt = 0; nt < 8; nt++) {
            const int row = rm + wm * 64 + mt * 16 + g;
            const int col = cn + wn * 64 + nt * 8 + t4 * 2;
            *(float2*)(g_P + (size_t)row * TDIM + col) =
                make_float2(acc[mt*8+nt][0] * scale, acc[mt*8+nt][1] * scale);
            *(float2*)(g_P + (size_t)(row + 8) * TDIM + col) =
                make_float2(acc[mt*8+nt][2] * scale, acc[mt*8+nt][3] * scale);
        }
    }
}

// ---------------------------------------------------------------------------
// Kernel 3: register-resident row softmax. 256 threads x 16 regs = 4096 row.
// One global read + one global write. Final store applies the 16-group
// involution permutation and tf32 rounding.
// ---------------------------------------------------------------------------
__global__ __launch_bounds__(256)
void k_softmax(const int* __restrict__ n_padd_p)
{
    const int r = blockIdx.x;
    const int np = *n_padd_p;
    const int tid = threadIdx.x;
    __shared__ float red[256];

    float* prow = g_P + (size_t)r * TDIM;

    if (r < np) {
        float4 z = make_float4(0.f, 0.f, 0.f, 0.f);
        for (int i = tid; i < TDIM / 4; i += 256)
            ((float4*)prow)[i] = z;
        return;
    }

    const int base = tid * 16;
    float v[16];
    #pragma unroll
    for (int j = 0; j < 16; j += 4)
        *(float4*)&v[j] = *(const float4*)&prow[base + j];

    // local max over valid cols [np, r]
    float m = -3.402823466e+38f;
    #pragma unroll
    for (int j = 0; j < 16; j++) {
        const int c = base + j;
        if (c >= np && c <= r) m = fmaxf(m, v[j]);
    }
    red[tid] = m; __syncthreads();
    for (int s = 128; s > 0; s >>= 1) {
        if (tid < s) red[tid] = fmaxf(red[tid], red[tid + s]);
        __syncthreads();
    }
    m = red[0];
    __syncthreads();

    // exp (invalid -> 0) + local sum
    float sum = 0.f;
    #pragma unroll
    for (int j = 0; j < 16; j++) {
        const int c = base + j;
        float e = (c >= np && c <= r) ? __expf(v[j] - m) : 0.f;
        v[j] = e;
        sum += e;
    }
    red[tid] = sum; __syncthreads();
    for (int s = 128; s > 0; s >>= 1) {
        if (tid < s) red[tid] += red[tid + s];
        __syncthreads();
    }
    const float inv = 1.0f / red[0];

    // normalize + round + permute (out[4a+b] = v[4b+a]) + single store
    #pragma unroll
    for (int j = 0; j < 16; j++) v[j] = f2tf32f(v[j] * inv);
    #pragma unroll
    for (int a = 0; a < 4; a++) {
        float4 o = make_float4(v[a], v[4 + a], v[8 + a], v[12 + a]);
        *(float4*)&prow[base + 4 * a] = o;
    }
}

// ---------------------------------------------------------------------------
// Kernel 4: y = P @ V (NT via g_vt, both t-permuted), K-range clipped.
// ---------------------------------------------------------------------------
__global__ __launch_bounds__(NTHR, 2)
void k_gemm_pv(const int* __restrict__ n_padd_p, float* __restrict__ C)
{
    const int np = *n_padd_p;
    const int rm = blockIdx.y * BM;
    const int cn = blockIdx.x * BN;
    const int tid = threadIdx.x;
    const int lane = tid & 31, wid = tid >> 5;
    const int wm = wid & 1, wn = wid >> 1;
    const int g = lane >> 2, t4 = lane & 3;

    if (rm + BM <= np) {
        for (int idx = tid; idx < BM * (BN / 4); idx += NTHR) {
            int row = idx / (BN / 4);
            int c4 = idx % (BN / 4);
            ((float4*)(C + (size_t)(rm + row) * NF + cn))[c4] =
                make_float4(0.f, 0.f, 0.f, 0.f);
        }
        return;
    }

    const int kstart = np & ~(BK - 1);
    const int nk = (rm + BM - kstart) / BK;

    extern __shared__ float sm[];

    float acc[32][4];
    #pragma unroll
    for (int i = 0; i < 32; i++)
        #pragma unroll
        for (int j = 0; j < 4; j++) acc[i][j] = 0.f;

    const float* pa = g_P + (size_t)rm * TDIM;
    const float* pb = g_vt + (size_t)cn * TDIM;
    GEMM_MAINLOOP(pa, TDIM, pb, TDIM, kstart, nk);

    #pragma unroll
    for (int mt = 0; mt < 4; mt++) {
        #pragma unroll
        for (int nt = 0; nt < 8; nt++) {
            const int row = rm + wm * 64 + mt * 16 + g;
            const int col = cn + wn * 64 + nt * 8 + t4 * 2;
            *(float2*)(C + (size_t)row * NF + col) =
                make_float2(acc[mt*8+nt][0], acc[mt*8+nt][1]);
            *(float2*)(C + (size_t)(row + 8) * NF + col) =
                make_float2(acc[mt*8+nt][2], acc[mt*8+nt][3]);
        }
    }
}

// ---------------------------------------------------------------------------
extern "C" void kernel_launch(void* const* d_in, const int* in_sizes, int n_in,
                              void* d_out, int out_size)
{
    const float* x  = (const float*)d_in[0];
    const float* W  = (const float*)d_in[1];
    const float* b  = (const float*)d_in[2];
    const int*   np = (const int*)d_in[3];
    float* y = (float*)d_out;
    (void)in_sizes; (void)n_in; (void)out_size;

    cudaFuncSetAttribute(k_gemm_qkv, cudaFuncAttributeMaxDynamicSharedMemorySize, SMEM_TOT);
    cudaFuncSetAttribute(k_gemm_s,   cudaFuncAttributeMaxDynamicSharedMemorySize, SMEM_TOT);
    cudaFuncSetAttribute(k_gemm_pv,  cudaFuncAttributeMaxDynamicSharedMemorySize, SMEM_TOT);

    float* xr; float* wt;
    cudaGetSymbolAddress((void**)&xr, g_xr);
    cudaGetSymbolAddress((void**)&wt, g_wt);

    dim3 t256(256);
    dim3 tg(NTHR);
    k_round_perm<<<1024, t256>>>(x, xr, TDIM, CDIM);
    k_transpose_round_perm<<<dim3(N3 / 32, CDIM / 32), t256>>>(W, wt);
    k_gemm_qkv<<<dim3(N3 / BN, TDIM / BM), tg, SMEM_TOT>>>(b, np);
    k_transpose_v<<<dim3(NF / 32, TDIM / 32), t256>>>();
    k_gemm_s<<<dim3(TDIM / BN, TDIM / BM), tg, SMEM_TOT>>>(np);
    k_softmax<<<TDIM, t256>>>(np);
    k_gemm_pv<<<dim3(NF / BN, TDIM / BM), tg, SMEM_TOT>>>(np, y);
}